// round 13
// baseline (speedup 1.0000x reference)
#include <cuda_runtime.h>
#include <cuda_fp16.h>
#include <math.h>

#define BB 2
#define NN 2048
#define CC 64
#define NK 9
#define KC 576            // NK * CC
#define GG 5              // 5x5 bins, cell 0.2 > prune radius 0.171
#define NCELL 25
#define CHUNK 82          // ceil(2048/25)

#define R2f     0.01f
#define DILf    0.05f
#define FULLM   0xffffffffu

// knorm = 315 / (64 * pi * R^9), R = 0.1
#define KNORMf ((float)(315.0 / (64.0 * 3.14159265358979323846 * 1e-9)))

// ---------------- scratch ---------------------------------------------------
__device__ float  g_coef[BB * NN];
// W4: [kc/2][o/2] -> 8B = halves (o0@kc0, o1@kc0, o0@kc1, o1@kc1)
__device__ __half g_W4[(KC / 2) * 32 * 4];
__device__ float  g_dcoefS[BB * NN * CC];   // SORTED rows: [b][slot][c]
__device__ float2 g_sPos[BB * NN + 32];     // sorted positions + sentinel pad
__device__ int    g_slotOf[BB * NN];        // orig j -> slot
__device__ int    g_origOf[BB * NN];        // slot -> orig j
__device__ int    g_cellCnt[BB * NCELL];
__device__ int    g_cellStart[BB * NCELL];

__device__ __forceinline__ int cell_of(float x, float y) {
    int cx = (int)(x * (float)GG); cx = min(GG - 1, max(0, cx));
    int cy = (int)(y * (float)GG); cy = min(GG - 1, max(0, cy));
    return cy * GG + cx;
}

// ---------------- setup: blocks 0-1 bin+coef; blocks 2+ weight pack ---------
__global__ __launch_bounds__(800) void setup_kernel(
        const float* __restrict__ locs,
        const float* __restrict__ density,
        const float* __restrict__ weight) {
    if (blockIdx.x >= BB) {
        // ---- weight conversion + sentinel ----
        int idx = (blockIdx.x - BB) * 800 + threadIdx.x;
        if (idx < CC * CC * NK) {
            int o = idx / (CC * NK);
            int r = idx - o * (CC * NK);
            int c = r / NK;
            int k = r - c * NK;
            int kc = k * CC + c;
            __half* h4 = reinterpret_cast<__half*>(g_W4);
            h4[(((kc >> 1) * 32 + (o >> 1)) << 2) + ((kc & 1) << 1) + (o & 1)]
                = __float2half_rn(weight[idx]);
        } else if (idx < CC * CC * NK + 32) {
            g_sPos[BB * NN + (idx - CC * CC * NK)] = make_float2(1e9f, 1e9f);
        }
        return;
    }

    // ---- binning + coef for batch b: match_any chunk binning ----
    __shared__ float2 s_pos[NN];
    __shared__ int    s_cell[NN];
    __shared__ int    s_hist[NCELL][NCELL];   // [chunk][cell]
    __shared__ int    s_base[NCELL][NCELL];   // [chunk][cell]
    __shared__ int    s_cnt[NCELL];
    __shared__ int    s_cs[NCELL];

    int b    = blockIdx.x;
    int tid  = threadIdx.x;
    int w    = tid >> 5;       // warp = chunk (warps 0..24)
    int lane = tid & 31;

    if (w < NCELL && lane < NCELL) s_hist[w][lane] = 0;

    for (int t = tid; t < NN; t += 800) {
        const float* lp = locs + (size_t)(b * NN + t) * 3;
        float x = lp[0], y = lp[1], im = lp[2];
        s_pos[t]  = make_float2(x, y);
        s_cell[t] = cell_of(x, y);
        g_coef[b * NN + t] = 1.0f / (im * density[b * NN + t]);
    }
    __syncthreads();

    int start = w * CHUNK;
    int end   = min(start + CHUNK, NN);

    // phase 1: per-chunk histogram via match_any (3 iterations)
    if (w < NCELL) {
        #pragma unroll
        for (int it = 0; it < 3; it++) {
            int i = start + it * 32 + lane;
            int cell = (i < end) ? s_cell[i] : -1;
            unsigned mk = __match_any_sync(FULLM, cell);
            int leader = __ffs(mk) - 1;
            if (cell >= 0 && lane == leader)
                s_hist[w][cell] += __popc(mk);
            __syncwarp();
        }
    }
    __syncthreads();

    // phase 2a: warp c scans chunk-counts for cell c
    if (w < NCELL) {
        int c = w;
        int h = (lane < NCELL) ? s_hist[lane][c] : 0;
        int incl = h;
        #pragma unroll
        for (int o = 1; o < 32; o <<= 1) {
            int v = __shfl_up_sync(FULLM, incl, o);
            if (lane >= o) incl += v;
        }
        if (lane < NCELL) s_base[lane][c] = incl - h;   // excl chunk prefix
        if (lane == NCELL - 1) s_cnt[c] = incl;         // cell total
    }
    __syncthreads();

    // phase 2b: warp 0 scans cell totals -> cellStart
    if (w == 0) {
        int v = (lane < NCELL) ? s_cnt[lane] : 0;
        int incl = v;
        #pragma unroll
        for (int o = 1; o < 32; o <<= 1) {
            int u = __shfl_up_sync(FULLM, incl, o);
            if (lane >= o) incl += u;
        }
        if (lane < NCELL) {
            s_cs[lane] = incl - v;
            g_cellStart[b * NCELL + lane] = incl - v;
            g_cellCnt[b * NCELL + lane]   = v;
        }
    }
    __syncthreads();

    // phase 2c: base[chunk][cell] += cellStart[cell]
    if (w < NCELL && lane < NCELL) s_base[lane][w] += s_cs[w];
    __syncthreads();

    // phase 3: ordered scatter via match_any (3 iterations)
    if (w < NCELL) {
        #pragma unroll
        for (int it = 0; it < 3; it++) {
            int i = start + it * 32 + lane;
            int cell = (i < end) ? s_cell[i] : -1;
            unsigned mk = __match_any_sync(FULLM, cell);
            int leader = __ffs(mk) - 1;
            int rank = __popc(mk & ((1u << lane) - 1u));
            if (cell >= 0) {
                int base = s_base[w][cell];
                int slot = base + rank;
                g_slotOf[b * NN + i]    = slot;
                g_origOf[b * NN + slot] = i;
                g_sPos[b * NN + slot]   = s_pos[i];
                if (lane == leader) s_base[w][cell] = base + __popc(mk);
            }
            __syncwarp();
        }
    }
}

// ---------------- prep2: transpose data -> SORTED dcoefS --------------------
__global__ __launch_bounds__(256) void prep2_kernel(const float* __restrict__ data) {
    __shared__ float s[32][33];
    int jt = blockIdx.x;      // 0..63
    int ct = blockIdx.y;      // 0..1
    int b  = blockIdx.z;      // 0..1
    int tx = threadIdx.x;     // 0..31
    int ty = threadIdx.y;     // 0..7

    #pragma unroll
    for (int i = 0; i < 4; i++) {
        int c = ct * 32 + ty + 8 * i;
        s[ty + 8 * i][tx] = data[((size_t)(b * CC + c)) * NN + jt * 32 + tx];
    }
    __syncthreads();
    #pragma unroll
    for (int i = 0; i < 4; i++) {
        int j2 = jt * 32 + ty + 8 * i;
        int slot = g_slotOf[b * NN + j2];
        g_dcoefS[((size_t)(b * NN + slot)) * CC + ct * 32 + tx] =
            s[tx][ty + 8 * i] * g_coef[b * NN + j2];
    }
}

// ---------------- main: 2 warps/particle, slim entries + pipelined drain ----
__device__ __forceinline__ float wfun(float t) {
    t = fmaxf(t, 0.0f);
    return (t * t) * (t * KNORMf);
}

#define WBF 640   // floats per warp region (2560B): 33*12=396 entry floats, 576 deposit

__global__ __launch_bounds__(128, 9) void convsp_main_kernel(
        const float* __restrict__ bias, float* __restrict__ out) {
    __shared__ __align__(16) float buf[4][WBF];       // 10.25 KB
    __shared__ __align__(16) float2 part[2][32];      // pair partial results

    int b    = blockIdx.x >> 10;          // 2048 blocks: 1024 per batch
    int tid  = threadIdx.x;
    int warp = tid >> 5;                  // 0..3
    int lane = tid & 31;
    int p    = warp >> 1;                 // particle in block: 0..1
    int half = warp & 1;                  // which warp of the pair

    int i_slot = (blockIdx.x & 1023) * 2 + p;         // SORTED order
    const float2* sp = g_sPos + (size_t)b * NN;

    float2 pi = __ldg(&sp[i_slot]);
    float xi = pi.x, yi = pi.y;

    int cx = min(GG - 1, max(0, (int)(xi * (float)GG)));
    int cy = min(GG - 1, max(0, (int)(yi * (float)GG)));
    int cx0 = max(0, cx - 1), cx1 = min(GG - 1, cx + 1);
    int cy0 = max(0, cy - 1), cy1 = min(GG - 1, cy + 1);

    float a0x = 0.f, a1x = 0.f, a2x = 0.f, a3x = 0.f, a4x = 0.f,
          a5x = 0.f, a6x = 0.f, a7x = 0.f, a8x = 0.f;
    float a0y = 0.f, a1y = 0.f, a2y = 0.f, a3y = 0.f, a4y = 0.f,
          a5y = 0.f, a6y = 0.f, a7y = 0.f, a8y = 0.f;

    const float2* dcF = reinterpret_cast<const float2*>(g_dcoefS)
                        + ((size_t)b * NN * 32) + lane;

    float* wbF = buf[warp];

    for (int yy = cy0; yy <= cy1; yy++) {
        int c0 = b * NCELL + yy * GG + cx0;
        int c1 = b * NCELL + yy * GG + cx1;
        int rs = __ldg(&g_cellStart[c0]);
        int re = __ldg(&g_cellStart[c1]) + __ldg(&g_cellCnt[c1]);

        // pair-split: this warp takes alternating 32-wide tiles
        for (int t = rs + half * 32; t < re; t += 64) {
            // ---- Phase A: lane-parallel w-compute + compaction ----
            int slot = t + lane;
            float2 pj = __ldg(&sp[slot]);     // sentinel pad covers tail
            float dx = xi - pj.x;
            float dy = yi - pj.y;
            if (slot >= re) dx = 1e9f;

            float bxm = dx - DILf, bxp = dx + DILf;
            float bym = dy - DILf, byp = dy + DILf;
            float rx0 = fmaf(-bxm, bxm, R2f);
            float rx1 = fmaf(-dx,  dx,  R2f);
            float rx2 = fmaf(-bxp, bxp, R2f);
            float ay0 = bym * bym;
            float ay1 = dy * dy;
            float ay2 = byp * byp;

            float w0 = wfun(rx0 - ay0);
            float w1 = wfun(rx0 - ay1);
            float w2 = wfun(rx0 - ay2);
            float w3 = wfun(rx1 - ay0);
            float w4 = wfun(rx1 - ay1);
            float w5 = wfun(rx1 - ay2);
            float w6 = wfun(rx2 - ay0);
            float w7 = wfun(rx2 - ay1);
            float w8 = wfun(rx2 - ay2);

            // exact union test: some rx_a - ay_b > 0  <=>  some w > 0
            bool active = fmaxf(rx0, fmaxf(rx1, rx2)) >
                          fminf(ay0, fminf(ay1, ay2));

            unsigned m = __ballot_sync(FULLM, active);
            int cnt = __popc(m);
            if (active) {
                int rank = __popc(m & ((1u << lane) - 1u));
                float* e = wbF + rank * 12;
                *reinterpret_cast<float4*>(e + 0) =
                    make_float4(w0, w1, w2, w3);
                *reinterpret_cast<float4*>(e + 4) =
                    make_float4(w4, w5, w6, w7);
                *reinterpret_cast<float4*>(e + 8) =
                    make_float4(w8, __int_as_float(slot), 0.f, 0.f);
            }
            // sentinel entry at rank cnt (prefetch target, never FMA'd)
            if (lane == 0)
                *reinterpret_cast<float4*>(wbF + cnt * 12 + 8) =
                    make_float4(0.f, __int_as_float(0), 0.f, 0.f);
            __syncwarp();

            // ---- Phase B: entry-serial, software-pipelined dc load ----
            if (cnt > 0) {
                float4 q2 = *reinterpret_cast<const float4*>(wbF + 8);
                float2 dc = __ldg(&dcF[(size_t)__float_as_int(q2.y) << 5]);
                float w8c = q2.x;
                for (int e = 0; e < cnt; e++) {
                    const float* ep = wbF + e * 12;
                    float4 q2n = *reinterpret_cast<const float4*>(ep + 20);
                    float2 dcn = __ldg(
                        &dcF[(size_t)__float_as_int(q2n.y) << 5]);
                    float4 q0 = *reinterpret_cast<const float4*>(ep + 0);
                    float4 q1 = *reinterpret_cast<const float4*>(ep + 4);
                    a0x = fmaf(q0.x, dc.x, a0x); a0y = fmaf(q0.x, dc.y, a0y);
                    a1x = fmaf(q0.y, dc.x, a1x); a1y = fmaf(q0.y, dc.y, a1y);
                    a2x = fmaf(q0.z, dc.x, a2x); a2y = fmaf(q0.z, dc.y, a2y);
                    a3x = fmaf(q0.w, dc.x, a3x); a3y = fmaf(q0.w, dc.y, a3y);
                    a4x = fmaf(q1.x, dc.x, a4x); a4y = fmaf(q1.x, dc.y, a4y);
                    a5x = fmaf(q1.y, dc.x, a5x); a5y = fmaf(q1.y, dc.y, a5y);
                    a6x = fmaf(q1.z, dc.x, a6x); a6y = fmaf(q1.z, dc.y, a6y);
                    a7x = fmaf(q1.w, dc.x, a7x); a7y = fmaf(q1.w, dc.y, a7y);
                    a8x = fmaf(w8c,  dc.x, a8x); a8y = fmaf(w8c,  dc.y, a8y);
                    w8c = q2n.x;
                    dc  = dcn;
                }
            }
            __syncwarp();
        }
    }

    // ---- deposit partial field (576 floats) into this warp's smem buf ----
    __syncwarp();
    {
        float2* wf2 = reinterpret_cast<float2*>(wbF);
        wf2[0 * 32 + lane] = make_float2(a0x, a0y);
        wf2[1 * 32 + lane] = make_float2(a1x, a1y);
        wf2[2 * 32 + lane] = make_float2(a2x, a2y);
        wf2[3 * 32 + lane] = make_float2(a3x, a3y);
        wf2[4 * 32 + lane] = make_float2(a4x, a4y);
        wf2[5 * 32 + lane] = make_float2(a5x, a5y);
        wf2[6 * 32 + lane] = make_float2(a6x, a6y);
        wf2[7 * 32 + lane] = make_float2(a7x, a7y);
        wf2[8 * 32 + lane] = make_float2(a8x, a8y);
    }
    __syncthreads();

    // ---- merge pair partials into buf[2p] (A: rows 0-3, B: rows 4-8) -----
    {
        float2* A2 = reinterpret_cast<float2*>(buf[2 * p]);
        float2* B2 = reinterpret_cast<float2*>(buf[2 * p + 1]);
        int r0r = half ? 4 : 0;
        int r1r = half ? 9 : 4;
        for (int r = r0r; r < r1r; r++) {
            float2 va = A2[r * 32 + lane];
            float2 vb = B2[r * 32 + lane];
            A2[r * 32 + lane] = make_float2(va.x + vb.x, va.y + vb.y);
        }
    }
    __syncthreads();

    // ---- fused GEMV over this warp's kc half; lane = o-pair (fp16 W4) ----
    // W4[kc2][o2]: one LDG.64 = weights for (2 kc x 2 o); 2 loads per quad.
    const float4* fq = reinterpret_cast<const float4*>(buf[2 * p]);
    const uint2*  w4 = reinterpret_cast<const uint2*>(g_W4) + lane;
    float p00 = 0.f, p01 = 0.f, p10 = 0.f, p11 = 0.f;
    float p20 = 0.f, p21 = 0.f, p30 = 0.f, p31 = 0.f;

    int q0i = half * (KC / 8);           // 72 quad-iters per warp
    #pragma unroll 4
    for (int q = q0i; q < q0i + KC / 8; q++) {
        float4 f4 = fq[q];
        uint2 u0 = __ldg(&w4[(2 * q + 0) * 32]);   // kc 4q, 4q+1
        uint2 u1 = __ldg(&w4[(2 * q + 1) * 32]);   // kc 4q+2, 4q+3
        float2 v0 = __half22float2(*reinterpret_cast<const __half2*>(&u0.x));
        float2 v1 = __half22float2(*reinterpret_cast<const __half2*>(&u0.y));
        float2 v2 = __half22float2(*reinterpret_cast<const __half2*>(&u1.x));
        float2 v3 = __half22float2(*reinterpret_cast<const __half2*>(&u1.y));
        p00 = fmaf(v0.x, f4.x, p00); p01 = fmaf(v0.y, f4.x, p01);
        p10 = fmaf(v1.x, f4.y, p10); p11 = fmaf(v1.y, f4.y, p11);
        p20 = fmaf(v2.x, f4.z, p20); p21 = fmaf(v2.y, f4.z, p21);
        p30 = fmaf(v3.x, f4.w, p30); p31 = fmaf(v3.y, f4.w, p31);
    }
    float r0 = (p00 + p10) + (p20 + p30);
    float r1 = (p01 + p11) + (p21 + p31);

    if (half == 1) part[p][lane] = make_float2(r0, r1);
    __syncthreads();

    if (half == 0) {
        float2 pr = part[p][lane];
        int orig = __ldg(&g_origOf[b * NN + i_slot]);
        float2 bv = *reinterpret_cast<const float2*>(&bias[2 * lane]);
        out[((size_t)b * CC + 2 * lane)     * NN + orig] = bv.x + r0 + pr.x;
        out[((size_t)b * CC + 2 * lane + 1) * NN + orig] = bv.y + r1 + pr.y;
    }
}

// ---------------- launcher --------------------------------------------------
extern "C" void kernel_launch(void* const* d_in, const int* in_sizes, int n_in,
                              void* d_out, int out_size) {
    // Bind inputs by unique element counts:
    // locs 12288, data 262144, density 4096, weight 36864, bias 64.
    const float* locs = nullptr;
    const float* data = nullptr;
    const float* density = nullptr;
    const float* weight = nullptr;
    const float* bias = nullptr;
    for (int idx = 0; idx < n_in; idx++) {
        switch (in_sizes[idx]) {
            case 12288:  locs    = (const float*)d_in[idx]; break;
            case 262144: data    = (const float*)d_in[idx]; break;
            case 4096:   density = (const float*)d_in[idx]; break;
            case 36864:  weight  = (const float*)d_in[idx]; break;
            case 64:     bias    = (const float*)d_in[idx]; break;
            default: break;
        }
    }
    float* out = (float*)d_out;

    // 2 bin blocks + 47 weight blocks (47*800 = 37600 >= 36896)
    setup_kernel<<<BB + 47, 800>>>(locs, density, weight);
    prep2_kernel<<<dim3(64, 2, 2), dim3(32, 8)>>>(data);
    convsp_main_kernel<<<2048, 128>>>(bias, out);
}

// round 14
// speedup vs baseline: 1.6076x; 1.6076x over previous
#include <cuda_runtime.h>
#include <cuda_fp16.h>
#include <math.h>

#define BB 2
#define NN 2048
#define CC 64
#define NK 9
#define KC 576            // NK * CC
#define GG 5              // 5x5 bins, cell 0.2 > prune radius 0.171
#define NCELL 25
#define NCHUNK 8          // bin chunks: 8 warps x 256 particles

#define R2f     0.01f
#define DILf    0.05f
#define FULLM   0xffffffffu

// knorm = 315 / (64 * pi * R^9), R = 0.1
#define KNORMf ((float)(315.0 / (64.0 * 3.14159265358979323846 * 1e-9)))

// ---------------- scratch ---------------------------------------------------
// W4: [kc/2][o/2] -> 8B = halves (o0@kc0, o1@kc0, o0@kc1, o1@kc1)
__device__ __half g_W4[(KC / 2) * 32 * 4];
__device__ float  g_dcoefU[BB * NN * CC];   // UNSORTED rows: [b][j][c]
__device__ float2 g_sPos[BB * NN + 32];     // sorted positions + sentinel pad
__device__ int    g_origOf[BB * NN + 32];   // slot -> orig j (+pad for tails)
__device__ int    g_cellCnt[BB * NCELL];
__device__ int    g_cellStart[BB * NCELL];

__device__ __forceinline__ int cell_of(float x, float y) {
    int cx = (int)(x * (float)GG); cx = min(GG - 1, max(0, cx));
    int cy = (int)(y * (float)GG); cy = min(GG - 1, max(0, cy));
    return cy * GG + cx;
}

// ---------------- setup: ONE kernel, three independent roles ----------------
// blocks [0,256):   data transpose+scale -> dcoefU (computes coef inline)
// blocks [256,258): binning for batch b = blk-256 (match_any, 8 chunks)
// blocks [258,403): fp16 weight packing + sentinel init
__global__ __launch_bounds__(256) void setup_kernel(
        const float* __restrict__ locs,
        const float* __restrict__ density,
        const float* __restrict__ data,
        const float* __restrict__ weight) {
    __shared__ __align__(16) char smem_raw[26176];
    int blk = blockIdx.x;
    int tid = threadIdx.x;

    if (blk < 256) {
        // ---- transpose role: jt in [0,64), ct in [0,2), b in [0,2) ----
        float (*s)[33] = reinterpret_cast<float (*)[33]>(smem_raw);
        int jt = blk & 63;
        int ct = (blk >> 6) & 1;
        int b  = blk >> 7;
        int tx = tid & 31;
        int ty = tid >> 5;        // 0..7

        #pragma unroll
        for (int i = 0; i < 4; i++) {
            int c = ct * 32 + ty + 8 * i;
            s[ty + 8 * i][tx] =
                data[((size_t)(b * CC + c)) * NN + jt * 32 + tx];
        }
        __syncthreads();
        #pragma unroll
        for (int i = 0; i < 4; i++) {
            int j2 = jt * 32 + ty + 8 * i;
            float im  = locs[(size_t)(b * NN + j2) * 3 + 2];
            float den = density[b * NN + j2];
            float coef = 1.0f / (im * den);
            g_dcoefU[((size_t)(b * NN + j2)) * CC + ct * 32 + tx] =
                s[tx][ty + 8 * i] * coef;
        }
        return;
    }

    if (blk >= 258) {
        // ---- weight pack role + sentinel ----
        int idx = (blk - 258) * 256 + tid;
        if (idx < CC * CC * NK) {
            int o = idx / (CC * NK);
            int r = idx - o * (CC * NK);
            int c = r / NK;
            int k = r - c * NK;
            int kc = k * CC + c;
            __half* h4 = reinterpret_cast<__half*>(g_W4);
            h4[(((kc >> 1) * 32 + (o >> 1)) << 2) + ((kc & 1) << 1) + (o & 1)]
                = __float2half_rn(weight[idx]);
        } else if (idx < CC * CC * NK + 32) {
            int q = idx - CC * CC * NK;
            g_sPos[BB * NN + q]   = make_float2(1e9f, 1e9f);
            g_origOf[BB * NN + q] = 0;
        }
        return;
    }

    // ---- binning role: batch b, 8 warps x chunk 256 ----
    float2* s_pos  = reinterpret_cast<float2*>(smem_raw);            // 16384B
    int*    s_cell = reinterpret_cast<int*>(smem_raw + 16384);       //  8192B
    int*    s_hist = reinterpret_cast<int*>(smem_raw + 24576);       //   800B
    int*    s_base = reinterpret_cast<int*>(smem_raw + 25376);       //   800B

    int b    = blk - 256;
    int w    = tid >> 5;       // warp = chunk 0..7
    int lane = tid & 31;

    if (tid < NCHUNK * NCELL) s_hist[tid] = 0;

    for (int t = tid; t < NN; t += 256) {
        const float* lp = locs + (size_t)(b * NN + t) * 3;
        float x = lp[0], y = lp[1];
        s_pos[t]  = make_float2(x, y);
        s_cell[t] = cell_of(x, y);
    }
    __syncthreads();

    // phase 1: per-chunk histogram (8 iters, no bounds: 8*256 = 2048)
    #pragma unroll
    for (int it = 0; it < 8; it++) {
        int i = w * 256 + it * 32 + lane;
        int cell = s_cell[i];
        unsigned mk = __match_any_sync(FULLM, cell);
        if (lane == __ffs(mk) - 1) s_hist[w * NCELL + cell] += __popc(mk);
        __syncwarp();
    }
    __syncthreads();

    // phase 2: warp 0 computes bases + cellStart
    if (w == 0) {
        int tot = 0;
        if (lane < NCELL) {
            #pragma unroll
            for (int ch = 0; ch < NCHUNK; ch++) {
                s_base[ch * NCELL + lane] = tot;
                tot += s_hist[ch * NCELL + lane];
            }
        }
        int incl = (lane < NCELL) ? tot : 0;
        #pragma unroll
        for (int o = 1; o < 32; o <<= 1) {
            int v = __shfl_up_sync(FULLM, incl, o);
            if (lane >= o) incl += v;
        }
        if (lane < NCELL) {
            int cs = incl - tot;
            g_cellStart[b * NCELL + lane] = cs;
            g_cellCnt[b * NCELL + lane]   = tot;
            #pragma unroll
            for (int ch = 0; ch < NCHUNK; ch++)
                s_base[ch * NCELL + lane] += cs;
        }
    }
    __syncthreads();

    // phase 3: ordered scatter (cell, j) via match_any
    #pragma unroll
    for (int it = 0; it < 8; it++) {
        int i = w * 256 + it * 32 + lane;
        int cell = s_cell[i];
        unsigned mk = __match_any_sync(FULLM, cell);
        int rank = __popc(mk & ((1u << lane) - 1u));
        int base = s_base[w * NCELL + cell];
        int slot = base + rank;
        g_origOf[b * NN + slot] = i;
        g_sPos[b * NN + slot]   = s_pos[i];
        if (lane == __ffs(mk) - 1)
            s_base[w * NCELL + cell] = base + __popc(mk);
        __syncwarp();
    }
}

// ---------------- main: 2 warps/particle, slim entries + pipelined drain ----
__device__ __forceinline__ float wfun(float t) {
    t = fmaxf(t, 0.0f);
    return (t * t) * (t * KNORMf);
}

#define WBF 640   // floats per warp region (2560B): 33*12=396 entry floats, 576 deposit

__global__ __launch_bounds__(128, 9) void convsp_main_kernel(
        const float* __restrict__ bias, float* __restrict__ out) {
    __shared__ __align__(16) float buf[4][WBF];       // 10.25 KB
    __shared__ __align__(16) float2 part[2][32];      // pair partial results

    int b    = blockIdx.x >> 10;          // 2048 blocks: 1024 per batch
    int tid  = threadIdx.x;
    int warp = tid >> 5;                  // 0..3
    int lane = tid & 31;
    int p    = warp >> 1;                 // particle in block: 0..1
    int half = warp & 1;                  // which warp of the pair

    int i_slot = (blockIdx.x & 1023) * 2 + p;         // SORTED order
    const float2* sp = g_sPos + (size_t)b * NN;
    const int*    og = g_origOf + (size_t)b * NN;

    float2 pi = __ldg(&sp[i_slot]);
    float xi = pi.x, yi = pi.y;

    int cx = min(GG - 1, max(0, (int)(xi * (float)GG)));
    int cy = min(GG - 1, max(0, (int)(yi * (float)GG)));
    int cx0 = max(0, cx - 1), cx1 = min(GG - 1, cx + 1);
    int cy0 = max(0, cy - 1), cy1 = min(GG - 1, cy + 1);

    float a0x = 0.f, a1x = 0.f, a2x = 0.f, a3x = 0.f, a4x = 0.f,
          a5x = 0.f, a6x = 0.f, a7x = 0.f, a8x = 0.f;
    float a0y = 0.f, a1y = 0.f, a2y = 0.f, a3y = 0.f, a4y = 0.f,
          a5y = 0.f, a6y = 0.f, a7y = 0.f, a8y = 0.f;

    const float2* dcF = reinterpret_cast<const float2*>(g_dcoefU)
                        + ((size_t)b * NN * 32) + lane;

    float* wbF = buf[warp];

    for (int yy = cy0; yy <= cy1; yy++) {
        int c0 = b * NCELL + yy * GG + cx0;
        int c1 = b * NCELL + yy * GG + cx1;
        int rs = __ldg(&g_cellStart[c0]);
        int re = __ldg(&g_cellStart[c1]) + __ldg(&g_cellCnt[c1]);

        // pair-split: this warp takes alternating 32-wide tiles
        for (int t = rs + half * 32; t < re; t += 64) {
            // ---- Phase A: lane-parallel w-compute + compaction ----
            int slot = t + lane;
            float2 pj = __ldg(&sp[slot]);     // sentinel pad covers tail
            int orig  = __ldg(&og[slot]);     // padded array covers tail
            float dx = xi - pj.x;
            float dy = yi - pj.y;
            if (slot >= re) dx = 1e9f;

            float bxm = dx - DILf, bxp = dx + DILf;
            float bym = dy - DILf, byp = dy + DILf;
            float rx0 = fmaf(-bxm, bxm, R2f);
            float rx1 = fmaf(-dx,  dx,  R2f);
            float rx2 = fmaf(-bxp, bxp, R2f);
            float ay0 = bym * bym;
            float ay1 = dy * dy;
            float ay2 = byp * byp;

            float w0 = wfun(rx0 - ay0);
            float w1 = wfun(rx0 - ay1);
            float w2 = wfun(rx0 - ay2);
            float w3 = wfun(rx1 - ay0);
            float w4 = wfun(rx1 - ay1);
            float w5 = wfun(rx1 - ay2);
            float w6 = wfun(rx2 - ay0);
            float w7 = wfun(rx2 - ay1);
            float w8 = wfun(rx2 - ay2);

            // exact union test: some rx_a - ay_b > 0  <=>  some w > 0
            bool active = fmaxf(rx0, fmaxf(rx1, rx2)) >
                          fminf(ay0, fminf(ay1, ay2));

            unsigned m = __ballot_sync(FULLM, active);
            int cnt = __popc(m);
            if (active) {
                int rank = __popc(m & ((1u << lane) - 1u));
                float* e = wbF + rank * 12;
                *reinterpret_cast<float4*>(e + 0) =
                    make_float4(w0, w1, w2, w3);
                *reinterpret_cast<float4*>(e + 4) =
                    make_float4(w4, w5, w6, w7);
                *reinterpret_cast<float4*>(e + 8) =
                    make_float4(w8, __int_as_float(orig), 0.f, 0.f);
            }
            // sentinel entry at rank cnt (prefetch target, never FMA'd)
            if (lane == 0)
                *reinterpret_cast<float4*>(wbF + cnt * 12 + 8) =
                    make_float4(0.f, __int_as_float(0), 0.f, 0.f);
            __syncwarp();

            // ---- Phase B: entry-serial, software-pipelined dc load ----
            if (cnt > 0) {
                float4 q2 = *reinterpret_cast<const float4*>(wbF + 8);
                float2 dc = __ldg(&dcF[(size_t)__float_as_int(q2.y) << 5]);
                float w8c = q2.x;
                for (int e = 0; e < cnt; e++) {
                    const float* ep = wbF + e * 12;
                    float4 q2n = *reinterpret_cast<const float4*>(ep + 20);
                    float2 dcn = __ldg(
                        &dcF[(size_t)__float_as_int(q2n.y) << 5]);
                    float4 q0 = *reinterpret_cast<const float4*>(ep + 0);
                    float4 q1 = *reinterpret_cast<const float4*>(ep + 4);
                    a0x = fmaf(q0.x, dc.x, a0x); a0y = fmaf(q0.x, dc.y, a0y);
                    a1x = fmaf(q0.y, dc.x, a1x); a1y = fmaf(q0.y, dc.y, a1y);
                    a2x = fmaf(q0.z, dc.x, a2x); a2y = fmaf(q0.z, dc.y, a2y);
                    a3x = fmaf(q0.w, dc.x, a3x); a3y = fmaf(q0.w, dc.y, a3y);
                    a4x = fmaf(q1.x, dc.x, a4x); a4y = fmaf(q1.x, dc.y, a4y);
                    a5x = fmaf(q1.y, dc.x, a5x); a5y = fmaf(q1.y, dc.y, a5y);
                    a6x = fmaf(q1.z, dc.x, a6x); a6y = fmaf(q1.z, dc.y, a6y);
                    a7x = fmaf(q1.w, dc.x, a7x); a7y = fmaf(q1.w, dc.y, a7y);
                    a8x = fmaf(w8c,  dc.x, a8x); a8y = fmaf(w8c,  dc.y, a8y);
                    w8c = q2n.x;
                    dc  = dcn;
                }
            }
            __syncwarp();
        }
    }

    // ---- deposit partial field (576 floats) into this warp's smem buf ----
    __syncwarp();
    {
        float2* wf2 = reinterpret_cast<float2*>(wbF);
        wf2[0 * 32 + lane] = make_float2(a0x, a0y);
        wf2[1 * 32 + lane] = make_float2(a1x, a1y);
        wf2[2 * 32 + lane] = make_float2(a2x, a2y);
        wf2[3 * 32 + lane] = make_float2(a3x, a3y);
        wf2[4 * 32 + lane] = make_float2(a4x, a4y);
        wf2[5 * 32 + lane] = make_float2(a5x, a5y);
        wf2[6 * 32 + lane] = make_float2(a6x, a6y);
        wf2[7 * 32 + lane] = make_float2(a7x, a7y);
        wf2[8 * 32 + lane] = make_float2(a8x, a8y);
    }
    __syncthreads();

    // ---- merge pair partials into buf[2p] (A: rows 0-3, B: rows 4-8) -----
    {
        float2* A2 = reinterpret_cast<float2*>(buf[2 * p]);
        float2* B2 = reinterpret_cast<float2*>(buf[2 * p + 1]);
        int r0r = half ? 4 : 0;
        int r1r = half ? 9 : 4;
        for (int r = r0r; r < r1r; r++) {
            float2 va = A2[r * 32 + lane];
            float2 vb = B2[r * 32 + lane];
            A2[r * 32 + lane] = make_float2(va.x + vb.x, va.y + vb.y);
        }
    }
    __syncthreads();

    // ---- fused GEMV over this warp's kc half; lane = o-pair (fp16 W4) ----
    // W4[kc2][o2]: one LDG.64 = weights for (2 kc x 2 o); 2 loads per quad.
    const float4* fq = reinterpret_cast<const float4*>(buf[2 * p]);
    const uint2*  w4 = reinterpret_cast<const uint2*>(g_W4) + lane;
    float p00 = 0.f, p01 = 0.f, p10 = 0.f, p11 = 0.f;
    float p20 = 0.f, p21 = 0.f, p30 = 0.f, p31 = 0.f;

    int q0i = half * (KC / 8);           // 72 quad-iters per warp
    #pragma unroll 4
    for (int q = q0i; q < q0i + KC / 8; q++) {
        float4 f4 = fq[q];
        uint2 u0 = __ldg(&w4[(2 * q + 0) * 32]);   // kc 4q, 4q+1
        uint2 u1 = __ldg(&w4[(2 * q + 1) * 32]);   // kc 4q+2, 4q+3
        float2 v0 = __half22float2(*reinterpret_cast<const __half2*>(&u0.x));
        float2 v1 = __half22float2(*reinterpret_cast<const __half2*>(&u0.y));
        float2 v2 = __half22float2(*reinterpret_cast<const __half2*>(&u1.x));
        float2 v3 = __half22float2(*reinterpret_cast<const __half2*>(&u1.y));
        p00 = fmaf(v0.x, f4.x, p00); p01 = fmaf(v0.y, f4.x, p01);
        p10 = fmaf(v1.x, f4.y, p10); p11 = fmaf(v1.y, f4.y, p11);
        p20 = fmaf(v2.x, f4.z, p20); p21 = fmaf(v2.y, f4.z, p21);
        p30 = fmaf(v3.x, f4.w, p30); p31 = fmaf(v3.y, f4.w, p31);
    }
    float r0 = (p00 + p10) + (p20 + p30);
    float r1 = (p01 + p11) + (p21 + p31);

    if (half == 1) part[p][lane] = make_float2(r0, r1);
    __syncthreads();

    if (half == 0) {
        float2 pr = part[p][lane];
        int orig = __ldg(&og[i_slot]);
        float2 bv = *reinterpret_cast<const float2*>(&bias[2 * lane]);
        out[((size_t)b * CC + 2 * lane)     * NN + orig] = bv.x + r0 + pr.x;
        out[((size_t)b * CC + 2 * lane + 1) * NN + orig] = bv.y + r1 + pr.y;
    }
}

// ---------------- launcher --------------------------------------------------
extern "C" void kernel_launch(void* const* d_in, const int* in_sizes, int n_in,
                              void* d_out, int out_size) {
    // Bind inputs by unique element counts:
    // locs 12288, data 262144, density 4096, weight 36864, bias 64.
    const float* locs = nullptr;
    const float* data = nullptr;
    const float* density = nullptr;
    const float* weight = nullptr;
    const float* bias = nullptr;
    for (int idx = 0; idx < n_in; idx++) {
        switch (in_sizes[idx]) {
            case 12288:  locs    = (const float*)d_in[idx]; break;
            case 262144: data    = (const float*)d_in[idx]; break;
            case 4096:   density = (const float*)d_in[idx]; break;
            case 36864:  weight  = (const float*)d_in[idx]; break;
            case 64:     bias    = (const float*)d_in[idx]; break;
            default: break;
        }
    }
    float* out = (float*)d_out;

    // 256 transpose + 2 bin + 145 weight blocks (145*256 = 37120 >= 36896)
    setup_kernel<<<403, 256>>>(locs, density, data, weight);
    convsp_main_kernel<<<2048, 128>>>(bias, out);
}